// round 3
// baseline (speedup 1.0000x reference)
#include <cuda_runtime.h>
#include <math.h>

#define AA 48
#define NDP 1128        // nondiag pairs
#define STEPS 23
#define ROW 1176        // AA + NDP
#define BPB 4           // batches per block
#define THREADS 320

__device__ float g_f4[NDP * 4];   // per-pair {f6,f8,f9,f12}
__device__ float g_sig[AA];       // sigmoid(emb_diag)
__device__ int   g_pair[NDP];     // ii | (jj<<8)

__global__ void setup_kernel(const float* __restrict__ ed,
                             const float* __restrict__ en) {
    int k = blockIdx.x * blockDim.x + threadIdx.x;
    if (k < AA) {
        g_sig[k] = 1.f / (1.f + expf(-ed[k]));
    }
    if (k < NDP) {
        float f12 = 1.f / (1.f + expf(-en[k * 4 + 0]));
        float f9  = 1.f / (1.f + expf(-en[k * 4 + 1])) * f12;
        float f8  = 1.f / (1.f + expf(-en[k * 4 + 2])) * f9;
        float f6  = 1.f / (1.f + expf(-en[k * 4 + 3])) * f8;
        g_f4[k * 4 + 0] = f6;
        g_f4[k * 4 + 1] = f8;
        g_f4[k * 4 + 2] = f9;
        g_f4[k * 4 + 3] = f12;
        // pair k -> (iy, ix) in row-major upper triangle, ix > iy
        int rem = k, iy = 0;
        while (rem >= AA - 1 - iy) { rem -= AA - 1 - iy; ++iy; }
        int ix = iy + 1 + rem;
        g_pair[k] = iy | (ix << 8);
    }
}

__global__ __launch_bounds__(THREADS)
void main_kernel(const int* __restrict__ x, float* __restrict__ out) {
    // byte-state scratch (written by recurrence, read by packer)
    __shared__ unsigned int       s_u32[BPB][STEPS][12];     // 4416 B
    // packed 2-bit state: col c -> u64 (c>>5), bits [2*(c&31) +: 2]
    __shared__ unsigned long long s_w[BPB][STEPS][2];        // 1472 B

    const int tid = threadIdx.x;
    const int b0  = blockIdx.x * BPB;

    // ---- phase 1: integer recurrence, one thread per (q, column) ----
    if (tid < BPB * AA) {
        int q = tid / AA;
        int j = tid - q * AA;
        const int* xb = x + (long)(b0 + q) * (25 * AA) + j;
        unsigned int v = 0;
        #pragma unroll
        for (int r = 0; r < 25; ++r)
            v |= ((unsigned int)__ldg(xb + r * AA)) << r;

        unsigned char* su = (unsigned char*)&s_u32[q][0][0];
        int st = -1, dt = 1;
        #pragma unroll
        for (int r = 0; r < STEPS; ++r) {
            int a  = (v >> r)       & 1;
            int bb = (v >> (r + 1)) & 1;
            int c  = (v >> (r + 2)) & 1;
            int de = a ^ c;
            int me = bb * (1 - (a + c)) + a * c;
            dt = dt * (1 - 2 * me);
            st = st + dt * de;
            st = st < -1 ? -1 : (st > 1 ? 1 : st);
            int ome = 1 - me;
            dt = dt * (1 - st * st * ome) - st * ome;
            su[r * AA + j] = (unsigned char)(st + 1);   // 0,1,2
        }
    }
    __syncthreads();

    // ---- phase 2: pack bytes -> 2-bit words (184 threads, one u64 each) ----
    // h=0: SMEM words 0..7  -> columns  0..31 -> s_w[..][0] bits 0..63
    // h=1: SMEM words 8..11 -> columns 32..47 -> s_w[..][1] bits 0..31
    if (tid < BPB * STEPS * 2) {
        int q  = tid / (STEPS * 2);
        int rr = tid - q * (STEPS * 2);
        int r  = rr >> 1;
        int h  = rr & 1;
        const unsigned int* pw = &s_u32[q][r][h * 8];
        const int nw = h ? 4 : 8;
        unsigned long long w = 0;
        #pragma unroll
        for (int w6 = 0; w6 < 8; ++w6) {
            if (w6 >= nw) break;
            unsigned int word = pw[w6];
            #pragma unroll
            for (int kb = 0; kb < 4; ++kb)
                w |= (unsigned long long)((word >> (8 * kb)) & 3u)
                     << (2 * (w6 * 4 + kb));
        }
        s_w[q][r][h] = w;
    }
    __syncthreads();

    // ---- phase 3: streaming output, one float4 column per thread ----
    const int k4 = tid;
    if (k4 >= ROW / 4) return;
    const int k0 = k4 * 4;

    // per-element constants (registers for the whole block)
    float v1[4], v2[4], v3[4], v4[4];
    int   shi[4], shj[4], wri[4], wrj[4];
    #pragma unroll
    for (int e = 0; e < 4; ++e) {
        int k = k0 + e;
        int ii, jj;
        if (k < AA) {                 // diag: ii==jj; cls 0->0, 3->sig, 5->1
            ii = jj = k;
            v1[e] = 0.f; v2[e] = 0.f; v4[e] = 0.f;
            v3[e] = __ldg(&g_sig[k]);
        } else {
            int kp = k - AA;
            int p  = __ldg(&g_pair[kp]);
            ii = p & 255; jj = p >> 8;
            const float4 f = __ldg((const float4*)g_f4 + kp);
            v1[e] = f.x;  // f6
            v2[e] = f.y;  // f8
            v3[e] = f.z;  // f9
            v4[e] = f.w;  // f12
        }
        wri[e] = ii >> 5;  shi[e] = 2 * (ii & 31);
        wrj[e] = jj >> 5;  shj[e] = 2 * (jj & 31);
    }

    for (int q = 0; q < BPB; ++q) {
        float* orow = out + ((long)(b0 + q) * STEPS) * ROW + k0;
        #pragma unroll 1
        for (int r = 0; r < STEPS; ++r) {
            const ulonglong2 wv =
                *reinterpret_cast<const ulonglong2*>(&s_w[q][r][0]);
            float vv[4];
            #pragma unroll
            for (int e = 0; e < 4; ++e) {
                unsigned int ui =
                    (unsigned int)((wri[e] ? wv.y : wv.x) >> shi[e]) & 3u;
                unsigned int uj =
                    (unsigned int)((wrj[e] ? wv.y : wv.x) >> shj[e]) & 3u;
                int cls = (int)(ui + uj) + ((ui && uj) ? 1 : 0);
                float val = (cls == 5) ? 1.f :
                            (cls == 4) ? v4[e] :
                            (cls == 3) ? v3[e] :
                            (cls == 2) ? v2[e] :
                            (cls == 1) ? v1[e] : 0.f;
                vv[e] = val;
            }
            __stcs(reinterpret_cast<float4*>(orow + (long)r * ROW),
                   make_float4(vv[0], vv[1], vv[2], vv[3]));
        }
    }
}

extern "C" void kernel_launch(void* const* d_in, const int* in_sizes, int n_in,
                              void* d_out, int out_size) {
    const int*   x  = (const int*)d_in[0];     // (4096, 25, 48) int32
    const float* ed = (const float*)d_in[1];   // (1, 48) f32
    const float* en = (const float*)d_in[2];   // (1, 1128, 4) f32
    float* out = (float*)d_out;                // (4096, 23, 1176) f32

    setup_kernel<<<(NDP + 255) / 256, 256>>>(ed, en);
    int nb = in_sizes[0] / (25 * AA);          // 4096 batches
    main_kernel<<<nb / BPB, THREADS>>>(x, out);
}

// round 4
// speedup vs baseline: 1.7352x; 1.7352x over previous
#include <cuda_runtime.h>
#include <math.h>

#define AA 48
#define NDP 1128        // nondiag pairs
#define STEPS 23
#define ROW 1176        // AA + NDP
#define BPB 2           // batches per block
#define THREADS 320
#define LUTW 9          // per-column LUT width (cls = u'i + u'j in 0..8)

__device__ float g_lut[ROW * LUTW];  // unified per-output-column 9-entry LUT
__device__ int   g_pair[NDP];        // iy | (ix<<8)

__global__ void setup_kernel(const float* __restrict__ ed,
                             const float* __restrict__ en) {
    int k = blockIdx.x * blockDim.x + threadIdx.x;
    if (k < AA) {
        // diag column k: u'i == u'j -> sums {0,2,8} -> {0, sig, 1}
        float s = 1.f / (1.f + expf(-ed[k]));
        float* L = &g_lut[k * LUTW];
        #pragma unroll
        for (int c = 0; c < LUTW; ++c) L[c] = 0.f;
        L[2] = s;
        L[8] = 1.f;
    }
    if (k < NDP) {
        float f12 = 1.f / (1.f + expf(-en[k * 4 + 0]));
        float f9  = 1.f / (1.f + expf(-en[k * 4 + 1])) * f12;
        float f8  = 1.f / (1.f + expf(-en[k * 4 + 2])) * f9;
        float f6  = 1.f / (1.f + expf(-en[k * 4 + 3])) * f8;
        // u' in {0,1,4}: sums -> product classes:
        // 0:(2*2=4)->0  1:(2*3=6)->f6  2:(3*3=9)->f9
        // 4:(2*4=8)->f8 5:(3*4=12)->f12 8:(4*4=16)->1
        float* L = &g_lut[(AA + k) * LUTW];
        L[0] = 0.f; L[1] = f6; L[2] = f9; L[3] = 0.f;
        L[4] = f8;  L[5] = f12; L[6] = 0.f; L[7] = 0.f;
        L[8] = 1.f;
        // pair k -> (iy, ix), row-major upper triangle, ix > iy
        int rem = k, iy = 0;
        while (rem >= AA - 1 - iy) { rem -= AA - 1 - iy; ++iy; }
        int ix = iy + 1 + rem;
        g_pair[k] = iy | (ix << 8);
    }
}

__global__ __launch_bounds__(THREADS)
void main_kernel(const int* __restrict__ x, float* __restrict__ out) {
    __shared__ float         s_lut[ROW * LUTW];        // 42336 B
    __shared__ unsigned char s_u[BPB][STEPS][AA];      //  2208 B

    const int tid = threadIdx.x;
    const int b0  = blockIdx.x * BPB;

    // ---- LUT copy (float4, 2646 vectors) ----
    {
        const float4* src = reinterpret_cast<const float4*>(g_lut);
        float4*       dst = reinterpret_cast<float4*>(s_lut);
        #pragma unroll
        for (int i = tid; i < (ROW * LUTW) / 4; i += THREADS)
            dst[i] = __ldg(src + i);
    }

    // ---- phase 1: integer recurrence, one thread per (q, column) ----
    if (tid < BPB * AA) {
        int q = tid / AA;
        int j = tid - q * AA;
        const int* xb = x + (long)(b0 + q) * (25 * AA) + j;
        unsigned int v = 0;
        #pragma unroll
        for (int r = 0; r < 25; ++r)
            v |= ((unsigned int)__ldg(xb + r * AA)) << r;

        int st = -1, dt = 1;
        #pragma unroll
        for (int r = 0; r < STEPS; ++r) {
            int a  = (v >> r)       & 1;
            int bb = (v >> (r + 1)) & 1;
            int c  = (v >> (r + 2)) & 1;
            int de = a ^ c;
            int me = bb * (1 - (a + c)) + a * c;
            dt = dt * (1 - 2 * me);
            st = st + dt * de;
            st = st < -1 ? -1 : (st > 1 ? 1 : st);
            int ome = 1 - me;
            dt = dt * (1 - st * st * ome) - st * ome;
            int u = st + 1;                 // 0,1,2
            u = u + (u & 2);                // remap 2 -> 4
            s_u[q][r][j] = (unsigned char)u;
        }
    }
    __syncthreads();

    // ---- phase 3: one thread per column t, strided columns t+294e ----
    const int t = tid;
    if (t >= ROW / 4) return;   // 294 active threads

    int off_i[4], off_j[4], lutb[4];
    #pragma unroll
    for (int e = 0; e < 4; ++e) {
        int k = t + (ROW / 4) * e;
        int ii, jj;
        if (k < AA) { ii = jj = k; }
        else {
            int p = __ldg(&g_pair[k - AA]);
            ii = p & 255; jj = p >> 8;
        }
        off_i[e] = ii;
        off_j[e] = jj;
        lutb[e]  = k * LUTW;
    }

    #pragma unroll
    for (int q = 0; q < BPB; ++q) {
        const unsigned char* uq = &s_u[q][0][0];
        float* ob = out + ((long)(b0 + q) * STEPS) * ROW + t;
        for (int r = 0; r < STEPS; ++r) {
            const unsigned char* u = uq + r * AA;
            float* orow = ob + (long)r * ROW;
            #pragma unroll
            for (int e = 0; e < 4; ++e) {
                int cls = (int)u[off_i[e]] + (int)u[off_j[e]];
                __stcs(orow + (ROW / 4) * e, s_lut[lutb[e] + cls]);
            }
        }
    }
}

extern "C" void kernel_launch(void* const* d_in, const int* in_sizes, int n_in,
                              void* d_out, int out_size) {
    const int*   x  = (const int*)d_in[0];     // (4096, 25, 48) int32
    const float* ed = (const float*)d_in[1];   // (1, 48) f32
    const float* en = (const float*)d_in[2];   // (1, 1128, 4) f32
    float* out = (float*)d_out;                // (4096, 23, 1176) f32

    setup_kernel<<<(NDP + 255) / 256, 256>>>(ed, en);
    int nb = in_sizes[0] / (25 * AA);          // 4096 batches
    main_kernel<<<nb / BPB, THREADS>>>(x, out);
}